// round 2
// baseline (speedup 1.0000x reference)
#include <cuda_runtime.h>
#include <math.h>

#define NNODES 10000
#define NHID   128
#define NH     4
#define UCOLS  1024   // [xh(512) | res(512)]
#define EMAX   160000

// ---------------- scratch (device globals; no allocation allowed) ----------
__device__ float g_X0[NNODES * NHID];
__device__ float g_X1[NNODES * NHID];
__device__ float g_U [NNODES * UCOLS];
__device__ float g_as[NNODES * NH];
__device__ float g_ad[NNODES * NH];
__device__ int   g_deg[NNODES];
__device__ int   g_cur[NNODES];
__device__ int   g_off[NNODES + 1];
__device__ int   g_csr[EMAX];
__device__ int   g_is64;

// ---------------- helpers ---------------------------------------------------
__device__ __forceinline__ float lrelu(float x) { return x > 0.f ? x : 0.2f * x; }
__device__ __forceinline__ float eluf (float x) { return x > 0.f ? x : (expf(x) - 1.f); }

__device__ __forceinline__ int edge_at(const void* ei, int idx, int is64) {
    if (is64) return (int)((const long long*)ei)[idx];
    return ((const int*)ei)[idx];
}

// detect int64 vs int32 edge_index: for int64 (values < 2^31), all odd 32-bit
// words are zero. OR the odd words of the first 4096 words.
__global__ void detect_kernel(const void* ei) {
    __shared__ int acc[256];
    int t = threadIdx.x;
    const unsigned* w = (const unsigned*)ei;
    unsigned o = 0;
    #pragma unroll
    for (int i = 0; i < 8; i++) {
        int idx = (t + i * 256) * 2 + 1;   // odd words, first 4096 words
        o |= w[idx];
    }
    acc[t] = (int)(o != 0);
    __syncthreads();
    for (int s = 128; s > 0; s >>= 1) {
        if (t < s) acc[t] |= acc[t + s];
        __syncthreads();
    }
    if (t == 0) g_is64 = acc[0] ? 0 : 1;   // any nonzero odd word -> int32
}

// ---------------- CSR build -------------------------------------------------
__global__ void zero_kernel() {
    int i = blockIdx.x * blockDim.x + threadIdx.x;
    if (i < NNODES) { g_deg[i] = 0; g_cur[i] = 0; }
}

__global__ void count_kernel(const void* __restrict__ ei, int E) {
    int e = blockIdx.x * blockDim.x + threadIdx.x;
    if (e < E) atomicAdd(&g_deg[edge_at(ei, E + e, g_is64)], 1);
}

__global__ void scan_kernel(int n) {   // 1 block, 1024 threads
    __shared__ int part[1024];
    int t = threadIdx.x;
    const int chunk = 10;              // ceil(10000/1024)
    int base = t * chunk;
    int s = 0;
    for (int i = 0; i < chunk; i++) { int idx = base + i; if (idx < n) s += g_deg[idx]; }
    int own = s;
    part[t] = s;
    __syncthreads();
    for (int d = 1; d < 1024; d <<= 1) {
        int v = (t >= d) ? part[t - d] : 0;
        __syncthreads();
        part[t] += v;
        __syncthreads();
    }
    int run = part[t] - own;
    for (int i = 0; i < chunk; i++) {
        int idx = base + i;
        if (idx < n) { g_off[idx] = run; run += g_deg[idx]; }
    }
    if (t == 1023) g_off[n] = part[1023];
}

__global__ void scatter_kernel(const void* __restrict__ ei, int E) {
    int e = blockIdx.x * blockDim.x + threadIdx.x;
    if (e < E) {
        int is64 = g_is64;
        int d = edge_at(ei, E + e, is64);
        int p = g_off[d] + atomicAdd(&g_cur[d], 1);
        g_csr[p] = edge_at(ei, e, is64);
    }
}

// ---------------- pointer resolution for device scratch --------------------
__device__ __forceinline__ const float* rsel(const float* ext, int sel) {
    if (sel == 1) return g_X0;
    if (sel == 2) return g_X1;
    if (sel == 3) return g_U;
    return ext;
}
__device__ __forceinline__ float* wsel(float* ext, int sel) {
    if (sel == 1) return g_X0;
    if (sel == 2) return g_X1;
    if (sel == 3) return g_U;
    return ext;
}

// ---------------- GEMM: C[m, coff+n] = sum_k A[m,k]*B[n,k] (+bias)(+relu) ---
// A row-major [M,K], B row-major [N,K]. BM=128, BN=64, BK=32, 256 threads.
__global__ __launch_bounds__(256)
void gemm_kernel(const float* __restrict__ Aext, int Asel,
                 const float* __restrict__ B,
                 const float* __restrict__ bias,
                 float* __restrict__ Cext, int Csel,
                 int M, int N, int K, int ldc, int coff, int relu)
{
    const float* A = rsel(Aext, Asel);
    float* C = wsel(Cext, Csel);

    __shared__ float As[32][129];
    __shared__ float Bs[32][65];
    int tid = threadIdx.x;
    int bm = blockIdx.x * 128, bn = blockIdx.y * 64;
    int tx = tid & 15, ty = tid >> 4;
    float acc[8][4];
    #pragma unroll
    for (int i = 0; i < 8; i++)
        #pragma unroll
        for (int j = 0; j < 4; j++) acc[i][j] = 0.f;

    for (int kt = 0; kt < K; kt += 32) {
        #pragma unroll
        for (int i = 0; i < 16; i++) {          // A: 128x32 = 4096 elems
            int idx = i * 256 + tid;
            int m = idx >> 5, k = idx & 31;
            int gm = bm + m;
            As[k][m] = (gm < M) ? A[(size_t)gm * K + kt + k] : 0.f;
        }
        #pragma unroll
        for (int i = 0; i < 8; i++) {           // B: 64x32 = 2048 elems
            int idx = i * 256 + tid;
            int nn = idx >> 5, k = idx & 31;
            int gn = bn + nn;
            Bs[k][nn] = (gn < N) ? B[(size_t)gn * K + kt + k] : 0.f;
        }
        __syncthreads();
        #pragma unroll
        for (int k = 0; k < 32; k++) {
            float a[8], b[4];
            #pragma unroll
            for (int i = 0; i < 8; i++) a[i] = As[k][ty * 8 + i];
            #pragma unroll
            for (int j = 0; j < 4; j++) b[j] = Bs[k][tx * 4 + j];
            #pragma unroll
            for (int i = 0; i < 8; i++)
                #pragma unroll
                for (int j = 0; j < 4; j++) acc[i][j] = fmaf(a[i], b[j], acc[i][j]);
        }
        __syncthreads();
    }

    #pragma unroll
    for (int i = 0; i < 8; i++) {
        int gm = bm + ty * 8 + i;
        if (gm >= M) continue;
        #pragma unroll
        for (int j = 0; j < 4; j++) {
            int gn = bn + tx * 4 + j;
            if (gn >= N) continue;
            float v = acc[i][j];
            if (bias) v += bias[gn];
            if (relu) v = fmaxf(v, 0.f);
            C[(size_t)gm * ldc + coff + gn] = v;
        }
    }
}

// ---------------- per-node attention logits a_src/a_dst --------------------
__global__ __launch_bounds__(128)
void attn_kernel(const float* __restrict__ att_src,
                 const float* __restrict__ att_dst)
{
    int n = blockIdx.x;
    int lane = threadIdx.x & 31;
    int h = threadIdx.x >> 5;     // head 0..3
    const float* xr = g_U + (size_t)n * UCOLS + h * 128;
    float s0 = 0.f, s1 = 0.f;
    #pragma unroll
    for (int j = 0; j < 4; j++) {
        float v = xr[lane + j * 32];
        s0 += v * att_src[h * 128 + lane + j * 32];
        s1 += v * att_dst[h * 128 + lane + j * 32];
    }
    #pragma unroll
    for (int o = 16; o > 0; o >>= 1) {
        s0 += __shfl_down_sync(0xffffffffu, s0, o);
        s1 += __shfl_down_sync(0xffffffffu, s1, o);
    }
    if (lane == 0) { g_as[n * 4 + h] = s0; g_ad[n * 4 + h] = s1; }
}

// ---------------- GAT aggregation + fused GraphCON epilogue ----------------
// one block per destination node, 128 threads (thread = channel c)
__global__ __launch_bounds__(128)
void node_kernel(const float* __restrict__ gat_b, int out_sel)
{
    float* Xnew = wsel(nullptr, out_sel);
    const float* U = g_U;
    int d = blockIdx.x, t = threadIdx.x;
    __shared__ float red[512];
    __shared__ float sv[512];
    const float4* as4 = (const float4*)g_as;
    int e0 = g_off[d], e1 = g_off[d + 1];

    float4 adv4 = ((const float4*)g_ad)[d];
    float adv[4] = {adv4.x, adv4.y, adv4.z, adv4.w};
    float4 asd4 = as4[d];
    float asd[4] = {asd4.x, asd4.y, asd4.z, asd4.w};

    // self-loop logit
    float ls[4];
    #pragma unroll
    for (int h = 0; h < 4; h++) ls[h] = lrelu(asd[h] + adv[h]);

    // ---- pass 1: max over incoming edges (+self) ----
    float mx[4];
    #pragma unroll
    for (int h = 0; h < 4; h++) mx[h] = ls[h];
    for (int i = e0 + t; i < e1; i += 128) {
        int s = g_csr[i];
        float4 a4 = as4[s];
        float av[4] = {a4.x, a4.y, a4.z, a4.w};
        #pragma unroll
        for (int h = 0; h < 4; h++) mx[h] = fmaxf(mx[h], lrelu(av[h] + adv[h]));
    }
    #pragma unroll
    for (int h = 0; h < 4; h++) red[t * 4 + h] = mx[h];
    __syncthreads();
    for (int sd = 64; sd > 0; sd >>= 1) {
        if (t < sd) {
            #pragma unroll
            for (int h = 0; h < 4; h++)
                red[t * 4 + h] = fmaxf(red[t * 4 + h], red[(t + sd) * 4 + h]);
        }
        __syncthreads();
    }
    #pragma unroll
    for (int h = 0; h < 4; h++) mx[h] = red[h];
    __syncthreads();

    // ---- pass 2: sum of exp ----
    float sm[4];
    #pragma unroll
    for (int h = 0; h < 4; h++) sm[h] = (t == 0) ? expf(ls[h] - mx[h]) : 0.f;
    for (int i = e0 + t; i < e1; i += 128) {
        int s = g_csr[i];
        float4 a4 = as4[s];
        float av[4] = {a4.x, a4.y, a4.z, a4.w};
        #pragma unroll
        for (int h = 0; h < 4; h++) sm[h] += expf(lrelu(av[h] + adv[h]) - mx[h]);
    }
    #pragma unroll
    for (int h = 0; h < 4; h++) red[t * 4 + h] = sm[h];
    __syncthreads();
    for (int sd = 64; sd > 0; sd >>= 1) {
        if (t < sd) {
            #pragma unroll
            for (int h = 0; h < 4; h++)
                red[t * 4 + h] += red[(t + sd) * 4 + h];
        }
        __syncthreads();
    }
    float rcp[4];
    #pragma unroll
    for (int h = 0; h < 4; h++) rcp[h] = 1.f / red[h];

    // ---- pass 3: aggregate alpha * xh[src] ----
    const float* xd = U + (size_t)d * UCOLS;
    float acc[4];
    #pragma unroll
    for (int h = 0; h < 4; h++) {
        float w = expf(ls[h] - mx[h]) * rcp[h];
        acc[h] = w * xd[h * 128 + t];
    }
    for (int i = e0; i < e1; i++) {
        int s = g_csr[i];
        float4 a4 = as4[s];
        float av[4] = {a4.x, a4.y, a4.z, a4.w};
        const float* xr = U + (size_t)s * UCOLS;
        #pragma unroll
        for (int h = 0; h < 4; h++) {
            float w = expf(lrelu(av[h] + adv[h]) - mx[h]) * rcp[h];
            acc[h] = fmaf(w, xr[h * 128 + t], acc[h]);
        }
    }

    // ---- epilogue: v = conv + gat_b + res; z = mean_h elu(v[c*4+h]); X_new = z
    #pragma unroll
    for (int h = 0; h < 4; h++) {
        int j = h * 128 + t;
        sv[j] = acc[h] + gat_b[j] + xd[512 + j];
    }
    __syncthreads();
    float4 vv = ((const float4*)sv)[t];
    Xnew[(size_t)d * 128 + t] =
        0.25f * (eluf(vv.x) + eluf(vv.y) + eluf(vv.z) + eluf(vv.w));
}

// ---------------- host ------------------------------------------------------
extern "C" void kernel_launch(void* const* d_in, const int* in_sizes, int n_in,
                              void* d_out, int out_size)
{
    const float* x       = (const float*)d_in[0];
    const void*  ei      = d_in[1];
    const float* enc_w   = (const float*)d_in[2];
    const float* enc_b   = (const float*)d_in[3];
    const float* res_w   = (const float*)d_in[4];
    const float* res_b   = (const float*)d_in[5];
    const float* gat_w   = (const float*)d_in[6];
    const float* att_src = (const float*)d_in[7];
    const float* att_dst = (const float*)d_in[8];
    const float* gat_b   = (const float*)d_in[9];
    const float* dec_w   = (const float*)d_in[10];
    const float* dec_b   = (const float*)d_in[11];
    int E = in_sizes[1] / 2;

    // dtype sniff + CSR by destination (built once per call; reused by layers)
    detect_kernel<<<1, 256>>>(ei);
    zero_kernel<<<(NNODES + 255) / 256, 256>>>();
    count_kernel<<<(E + 255) / 256, 256>>>(ei, E);
    scan_kernel<<<1, 1024>>>(NNODES);
    scatter_kernel<<<(E + 255) / 256, 256>>>(ei, E);

    // encoder: X0 = relu(x @ enc_w^T + enc_b)   [10000,128]
    gemm_kernel<<<dim3(79, 2), 256>>>(x, 0, enc_w, enc_b, nullptr, 1,
                                      NNODES, 128, 256, 128, 0, 1);

    // layer 0: read X0 (sel 1), write X1 (sel 2)
    // layer 1: read X1 (sel 2), write X0 (sel 1)
    for (int layer = 0; layer < 2; layer++) {
        int in_sel  = (layer == 0) ? 1 : 2;
        int out_sel = (layer == 0) ? 2 : 1;
        // U[:, :512] = Xc @ gat_w^T ; U[:, 512:] = Xc @ res_w^T + res_b
        gemm_kernel<<<dim3(79, 8), 256>>>(nullptr, in_sel, gat_w, nullptr,
                                          nullptr, 3,
                                          NNODES, 512, 128, UCOLS, 0, 0);
        gemm_kernel<<<dim3(79, 8), 256>>>(nullptr, in_sel, res_w, res_b,
                                          nullptr, 3,
                                          NNODES, 512, 128, UCOLS, 512, 0);
        attn_kernel<<<NNODES, 128>>>(att_src, att_dst);
        node_kernel<<<NNODES, 128>>>(gat_b, out_sel);
    }

    // decoder: out = X0 @ dec_w^T + dec_b   [10000,40]
    gemm_kernel<<<dim3(79, 1), 256>>>(nullptr, 1, dec_w, dec_b,
                                      (float*)d_out, 0,
                                      NNODES, 40, 128, 40, 0, 0);
}

// round 3
// speedup vs baseline: 1.6947x; 1.6947x over previous
#include <cuda_runtime.h>
#include <math.h>

#define NNODES 10000
#define NHID   128
#define UC     1032   // U row: xh(512) | res(512) | a_src(4) | a_dst(4)
#define NB     1032
#define EMAX   160000

// ---------------- scratch (device globals; no allocation allowed) ----------
__device__ float g_X0[NNODES * NHID];
__device__ float g_X1[NNODES * NHID];
__device__ float g_U [NNODES * UC];
__device__ float g_B [NB * NHID];     // fused weights [1032,128]
__device__ float g_bias[NB];
__device__ int   g_deg[NNODES];
__device__ int   g_cur[NNODES];
__device__ int   g_off[NNODES + 1];
__device__ int   g_csr[EMAX];
__device__ int   g_is64;

// ---------------- helpers ---------------------------------------------------
__device__ __forceinline__ float lrelu(float x) { return x > 0.f ? x : 0.2f * x; }
__device__ __forceinline__ float eluf (float x) { return x > 0.f ? x : (expf(x) - 1.f); }

__device__ __forceinline__ const float* sel_ptr(const float* ext, int sel) {
    if (sel == 1) return g_X0;
    if (sel == 2) return g_X1;
    if (sel == 3) return g_U;
    if (sel == 4) return g_B;
    if (sel == 5) return g_bias;
    return ext;
}

__device__ __forceinline__ int edge_at(const void* ei, int idx, int is64) {
    if (is64) return (int)((const long long*)ei)[idx];
    return ((const int*)ei)[idx];
}

// detect int64 vs int32 edge_index: for int64 values < 2^31, odd 32-bit words
// are all zero over the first 4096 words.
__global__ void detect_kernel(const void* ei) {
    __shared__ int acc[256];
    int t = threadIdx.x;
    const unsigned* w = (const unsigned*)ei;
    unsigned o = 0;
    #pragma unroll
    for (int i = 0; i < 8; i++) o |= w[(t + i * 256) * 2 + 1];
    acc[t] = (int)(o != 0);
    __syncthreads();
    for (int s = 128; s > 0; s >>= 1) {
        if (t < s) acc[t] |= acc[t + s];
        __syncthreads();
    }
    if (t == 0) g_is64 = acc[0] ? 0 : 1;
}

// ---------------- CSR build -------------------------------------------------
__global__ void zero_kernel() {
    int i = blockIdx.x * blockDim.x + threadIdx.x;
    if (i < NNODES) { g_deg[i] = 0; g_cur[i] = 0; }
}

__global__ void count_kernel(const void* __restrict__ ei, int E) {
    int e = blockIdx.x * blockDim.x + threadIdx.x;
    if (e < E) atomicAdd(&g_deg[edge_at(ei, E + e, g_is64)], 1);
}

__global__ void scan_kernel(int n) {   // 1 block, 1024 threads
    __shared__ int part[1024];
    int t = threadIdx.x;
    const int chunk = 10;
    int base = t * chunk;
    int s = 0;
    for (int i = 0; i < chunk; i++) { int idx = base + i; if (idx < n) s += g_deg[idx]; }
    int own = s;
    part[t] = s;
    __syncthreads();
    for (int d = 1; d < 1024; d <<= 1) {
        int v = (t >= d) ? part[t - d] : 0;
        __syncthreads();
        part[t] += v;
        __syncthreads();
    }
    int run = part[t] - own;
    for (int i = 0; i < chunk; i++) {
        int idx = base + i;
        if (idx < n) { g_off[idx] = run; run += g_deg[idx]; }
    }
    if (t == 1023) g_off[n] = part[1023];
}

__global__ void scatter_kernel(const void* __restrict__ ei, int E) {
    int e = blockIdx.x * blockDim.x + threadIdx.x;
    if (e < E) {
        int is64 = g_is64;
        int d = edge_at(ei, E + e, is64);
        int p = g_off[d] + atomicAdd(&g_cur[d], 1);
        g_csr[p] = edge_at(ei, e, is64);
    }
}

// ---------------- fused weight build ----------------------------------------
// rows 0..511: gat_w | 512..1023: res_w | 1024..1027: fold(att_src) | 1028..1031: fold(att_dst)
__global__ __launch_bounds__(128)
void build_b_kernel(const float* __restrict__ gat_w,
                    const float* __restrict__ res_w,
                    const float* __restrict__ att_src,
                    const float* __restrict__ att_dst)
{
    int r = blockIdx.x;
    int t = threadIdx.x;
    if (r < 512) {
        g_B[r * 128 + t] = gat_w[r * 128 + t];
    } else if (r < 1024) {
        g_B[r * 128 + t] = res_w[(r - 512) * 128 + t];
    } else {
        int h = (r - 1024) & 3;
        const float* att = (r < 1028) ? att_src : att_dst;
        float s = 0.f;
        for (int c = 0; c < 128; c++)
            s = fmaf(att[h * 128 + c], gat_w[(size_t)(h * 128 + c) * 128 + t], s);
        g_B[r * 128 + t] = s;
    }
}

__global__ void build_bias_kernel(const float* __restrict__ res_b) {
    int i = blockIdx.x * blockDim.x + threadIdx.x;
    if (i < NB) {
        float v = 0.f;
        if (i >= 512 && i < 1024) v = res_b[i - 512];
        g_bias[i] = v;
    }
}

// ---------------- GEMM: C[m,n] = sum_k A[m,k]*B[n,k] (+bias)(+relu) --------
// A row-major [M,K], B row-major [N,K]. BM=128, BN=64, BK=16, 256 threads,
// double-buffered smem, float4 global loads + register prefetch.
__global__ __launch_bounds__(256)
void gemm_kernel(const float* __restrict__ Aext, int Asel,
                 const float* __restrict__ Bext, int Bsel,
                 const float* __restrict__ biasext, int bsel,
                 float* __restrict__ Cext, int Csel,
                 int M, int N, int K, int ldc, int relu)
{
    const float* A = sel_ptr(Aext, Asel);
    const float* B = sel_ptr(Bext, Bsel);
    const float* bias = sel_ptr(biasext, bsel);
    float* C = (Csel == 1) ? g_X0 : (Csel == 2) ? g_X1 : (Csel == 3) ? g_U : Cext;

    __shared__ float As[2][16][132];
    __shared__ float Bs[2][16][68];

    const int tid = threadIdx.x;
    const int bm = blockIdx.x * 128, bn = blockIdx.y * 64;
    const int tx = tid & 15, ty = tid >> 4;

    // A tile 128x16 = 512 float4, 2 per thread; B tile 64x16 = 256 float4, 1 per thread
    const int am0 = tid >> 2;            // 0..63  (q=0)
    const int am1 = 64 + (tid >> 2);     // 64..127 (q=1)
    const int ak4 = tid & 3;
    const int bn0 = tid >> 2;            // 0..63
    const int bk4 = tid & 3;

    float4 pa0, pa1, pb;
    const int nt = K >> 4;

    // prologue loads (kt = 0)
    {
        int gm0 = bm + am0, gm1 = bm + am1, gn = bn + bn0;
        pa0 = (gm0 < M) ? *(const float4*)(A + (size_t)gm0 * K + ak4 * 4) : make_float4(0, 0, 0, 0);
        pa1 = (gm1 < M) ? *(const float4*)(A + (size_t)gm1 * K + ak4 * 4) : make_float4(0, 0, 0, 0);
        pb  = (gn  < N) ? *(const float4*)(B + (size_t)gn  * K + bk4 * 4) : make_float4(0, 0, 0, 0);
    }
    {
        As[0][ak4 * 4 + 0][am0] = pa0.x; As[0][ak4 * 4 + 1][am0] = pa0.y;
        As[0][ak4 * 4 + 2][am0] = pa0.z; As[0][ak4 * 4 + 3][am0] = pa0.w;
        As[0][ak4 * 4 + 0][am1] = pa1.x; As[0][ak4 * 4 + 1][am1] = pa1.y;
        As[0][ak4 * 4 + 2][am1] = pa1.z; As[0][ak4 * 4 + 3][am1] = pa1.w;
        Bs[0][bk4 * 4 + 0][bn0] = pb.x;  Bs[0][bk4 * 4 + 1][bn0] = pb.y;
        Bs[0][bk4 * 4 + 2][bn0] = pb.z;  Bs[0][bk4 * 4 + 3][bn0] = pb.w;
    }
    __syncthreads();

    float acc[8][4];
    #pragma unroll
    for (int i = 0; i < 8; i++)
        #pragma unroll
        for (int j = 0; j < 4; j++) acc[i][j] = 0.f;

    for (int t = 0; t < nt; t++) {
        int cur = t & 1;
        if (t + 1 < nt) {
            int kt = (t + 1) << 4;
            int gm0 = bm + am0, gm1 = bm + am1, gn = bn + bn0;
            pa0 = (gm0 < M) ? *(const float4*)(A + (size_t)gm0 * K + kt + ak4 * 4) : make_float4(0, 0, 0, 0);
            pa1 = (gm1 < M) ? *(const float4*)(A + (size_t)gm1 * K + kt + ak4 * 4) : make_float4(0, 0, 0, 0);
            pb  = (gn  < N) ? *(const float4*)(B + (size_t)gn  * K + kt + bk4 * 4) : make_float4(0, 0, 0, 0);
        }
        #pragma unroll
        for (int k = 0; k < 16; k++) {
            float4 av0 = *(const float4*)&As[cur][k][ty * 8];
            float4 av1 = *(const float4*)&As[cur][k][ty * 8 + 4];
            float4 bv  = *(const float4*)&Bs[cur][k][tx * 4];
            float a[8] = {av0.x, av0.y, av0.z, av0.w, av1.x, av1.y, av1.z, av1.w};
            float b[4] = {bv.x, bv.y, bv.z, bv.w};
            #pragma unroll
            for (int i = 0; i < 8; i++)
                #pragma unroll
                for (int j = 0; j < 4; j++) acc[i][j] = fmaf(a[i], b[j], acc[i][j]);
        }
        if (t + 1 < nt) {
            int nxt = cur ^ 1;
            As[nxt][ak4 * 4 + 0][am0] = pa0.x; As[nxt][ak4 * 4 + 1][am0] = pa0.y;
            As[nxt][ak4 * 4 + 2][am0] = pa0.z; As[nxt][ak4 * 4 + 3][am0] = pa0.w;
            As[nxt][ak4 * 4 + 0][am1] = pa1.x; As[nxt][ak4 * 4 + 1][am1] = pa1.y;
            As[nxt][ak4 * 4 + 2][am1] = pa1.z; As[nxt][ak4 * 4 + 3][am1] = pa1.w;
            Bs[nxt][bk4 * 4 + 0][bn0] = pb.x;  Bs[nxt][bk4 * 4 + 1][bn0] = pb.y;
            Bs[nxt][bk4 * 4 + 2][bn0] = pb.z;  Bs[nxt][bk4 * 4 + 3][bn0] = pb.w;
            __syncthreads();
        }
    }

    #pragma unroll
    for (int i = 0; i < 8; i++) {
        int gm = bm + ty * 8 + i;
        if (gm >= M) continue;
        #pragma unroll
        for (int j = 0; j < 4; j++) {
            int gn = bn + tx * 4 + j;
            if (gn >= N) continue;
            float v = acc[i][j];
            if (bias) v += bias[gn];
            if (relu) v = fmaxf(v, 0.f);
            C[(size_t)gm * ldc + gn] = v;
        }
    }
}

// ---------------- GAT aggregation + fused GraphCON epilogue ----------------
// one block per destination node, 128 threads; thread t owns flat channels
// 4t..4t+3 which all live in head h = t>>5.
__global__ __launch_bounds__(128)
void node_kernel(const float* __restrict__ gat_b, int out_sel)
{
    float* Xnew = (out_sel == 1) ? g_X0 : g_X1;
    const int d = blockIdx.x, t = threadIdx.x;
    const int h = t >> 5, lane = t & 31;

    const float* ud = g_U + (size_t)d * UC;
    const float adv = ud[1028 + h];
    const float ls = lrelu(ud[1024 + h] + adv);
    const int e0 = g_off[d], e1 = g_off[d + 1];

    // ---- warp-level max over incoming logits (+self) ----
    float mx = ls;
    for (int i = e0 + lane; i < e1; i += 32) {
        int s = g_csr[i];
        mx = fmaxf(mx, lrelu(g_U[(size_t)s * UC + 1024 + h] + adv));
    }
    #pragma unroll
    for (int o = 16; o > 0; o >>= 1)
        mx = fmaxf(mx, __shfl_xor_sync(0xffffffffu, mx, o));

    // ---- fused pass: unnormalized weighted aggregate + weight sum ----
    float ws = expf(ls - mx);
    float ssum = ws;
    float4 xd4 = ((const float4*)ud)[t];
    float4 acc = make_float4(ws * xd4.x, ws * xd4.y, ws * xd4.z, ws * xd4.w);

    int i = e0;
    for (; i + 2 <= e1; i += 2) {
        int s0 = g_csr[i], s1 = g_csr[i + 1];
        const float* u0 = g_U + (size_t)s0 * UC;
        const float* u1 = g_U + (size_t)s1 * UC;
        float a0 = u0[1024 + h], a1 = u1[1024 + h];
        float4 v0 = ((const float4*)u0)[t];
        float4 v1 = ((const float4*)u1)[t];
        float w0 = expf(lrelu(a0 + adv) - mx);
        float w1 = expf(lrelu(a1 + adv) - mx);
        acc.x = fmaf(w0, v0.x, acc.x); acc.y = fmaf(w0, v0.y, acc.y);
        acc.z = fmaf(w0, v0.z, acc.z); acc.w = fmaf(w0, v0.w, acc.w);
        acc.x = fmaf(w1, v1.x, acc.x); acc.y = fmaf(w1, v1.y, acc.y);
        acc.z = fmaf(w1, v1.z, acc.z); acc.w = fmaf(w1, v1.w, acc.w);
        ssum += w0 + w1;
    }
    if (i < e1) {
        int s0 = g_csr[i];
        const float* u0 = g_U + (size_t)s0 * UC;
        float w0 = expf(lrelu(u0[1024 + h] + adv) - mx);
        float4 v0 = ((const float4*)u0)[t];
        acc.x = fmaf(w0, v0.x, acc.x); acc.y = fmaf(w0, v0.y, acc.y);
        acc.z = fmaf(w0, v0.z, acc.z); acc.w = fmaf(w0, v0.w, acc.w);
        ssum += w0;
    }

    // ---- epilogue: v = conv/ssum + gat_b + res; z = mean over 4 flat elems
    float rcp = 1.f / ssum;
    float4 gb = ((const float4*)gat_b)[t];
    float4 rs = ((const float4*)(ud + 512))[t];
    float z = 0.25f * (eluf(fmaf(acc.x, rcp, gb.x + rs.x)) +
                       eluf(fmaf(acc.y, rcp, gb.y + rs.y)) +
                       eluf(fmaf(acc.z, rcp, gb.z + rs.z)) +
                       eluf(fmaf(acc.w, rcp, gb.w + rs.w)));
    Xnew[(size_t)d * NHID + t] = z;
}

// ---------------- host ------------------------------------------------------
extern "C" void kernel_launch(void* const* d_in, const int* in_sizes, int n_in,
                              void* d_out, int out_size)
{
    const float* x       = (const float*)d_in[0];
    const void*  ei      = d_in[1];
    const float* enc_w   = (const float*)d_in[2];
    const float* enc_b   = (const float*)d_in[3];
    const float* res_w   = (const float*)d_in[4];
    const float* res_b   = (const float*)d_in[5];
    const float* gat_w   = (const float*)d_in[6];
    const float* att_src = (const float*)d_in[7];
    const float* att_dst = (const float*)d_in[8];
    const float* gat_b   = (const float*)d_in[9];
    const float* dec_w   = (const float*)d_in[10];
    const float* dec_b   = (const float*)d_in[11];
    int E = in_sizes[1] / 2;

    // dtype sniff + CSR by destination
    detect_kernel<<<1, 256>>>(ei);
    zero_kernel<<<(NNODES + 255) / 256, 256>>>();
    count_kernel<<<(E + 255) / 256, 256>>>(ei, E);
    scan_kernel<<<1, 1024>>>(NNODES);
    scatter_kernel<<<(E + 255) / 256, 256>>>(ei, E);

    // fused weight + bias build (layer-invariant)
    build_b_kernel<<<NB, 128>>>(gat_w, res_w, att_src, att_dst);
    build_bias_kernel<<<(NB + 255) / 256, 256>>>(res_b);

    // encoder: X0 = relu(x @ enc_w^T + enc_b)
    gemm_kernel<<<dim3(79, 2), 256>>>(x, 0, enc_w, 0, enc_b, 0, nullptr, 1,
                                      NNODES, 128, 256, 128, 1);

    for (int layer = 0; layer < 2; layer++) {
        int in_sel  = (layer == 0) ? 1 : 2;
        int out_sel = (layer == 0) ? 2 : 1;
        // fused: U = Xc @ [gat_w; res_w; folds]^T + [0; res_b; 0]
        gemm_kernel<<<dim3(79, 17), 256>>>(nullptr, in_sel, nullptr, 4,
                                           nullptr, 5, nullptr, 3,
                                           NNODES, NB, 128, UC, 0);
        node_kernel<<<NNODES, 128>>>(gat_b, out_sel);
    }

    // decoder
    gemm_kernel<<<dim3(79, 1), 256>>>(nullptr, 1, dec_w, 0, dec_b, 0,
                                      (float*)d_out, 0,
                                      NNODES, 40, 128, 40, 0);
}